// round 2
// baseline (speedup 1.0000x reference)
#include <cuda_runtime.h>

// SConv2dAvg: out[b,o,y,x] = sum_{c,r,s} input[b,c,2y+selh+r,2x+selw+s]*W[o,c,r,s] + bias[o]
// B=16, Cin=64, H=W=128, Cout=64, k=3x3, oh=ow=63, STRIDE=2.

#define OHW    63
#define NPIX   (63 * 63)        // 3969
#define CIN    64
#define COUT   64
#define NB     16
#define KTOT   576              // Cin*3*3
#define KPAD   580              // +4 pad: kills 4-way bank conflict on patch LDS.128
#define KC     144              // k-chunk of weight staged in smem
#define NCHUNK (KTOT / KC)      // 4
#define THREADS 256
#define SMEM_BYTES ((2 * NB * KPAD + KC * COUT) * 4)   // 74240 + 36864 = 111104

// Weight transposed to k-major [576][64] so chunk loads are coalesced.
__device__ float g_wT[KTOT * COUT];

__global__ void transpose_w_kernel(const float* __restrict__ w) {
    int idx = blockIdx.x * 256 + threadIdx.x;
    if (idx < KTOT * COUT) {
        int k = idx >> 6;
        int o = idx & 63;
        g_wT[idx] = w[o * KTOT + k];
    }
}

__global__ __launch_bounds__(THREADS, 2) void sconv_kernel(
    const float* __restrict__ input,
    const float* __restrict__ bias,
    const int*   __restrict__ selh,
    const int*   __restrict__ selw,
    float*       __restrict__ out)
{
    extern __shared__ float smem[];
    float* patch = smem;                    // [2][16][KPAD]
    float* wsh   = smem + 2 * NB * KPAD;    // [KC][64]

    const int tid = threadIdx.x;
    const int px0 = blockIdx.x * 2;

    int  base_in[2];
    bool valid[2];
#pragma unroll
    for (int p = 0; p < 2; p++) {
        int px   = px0 + p;
        valid[p] = (px < NPIX);
        int pxc  = valid[p] ? px : 0;
        int y    = pxc / OHW;
        int x    = pxc - y * OHW;
        base_in[p] = (2 * y + selh[pxc]) * 128 + (2 * x + selw[pxc]);
    }

    // Stage both pixels' patches: 2*16*576 elements, 72 per thread.
    for (int idx = tid; idx < 2 * NB * KTOT; idx += THREADS) {
        int p   = (idx >= NB * KTOT) ? 1 : 0;
        int rem = idx - p * (NB * KTOT);
        int b   = rem / KTOT;
        int k   = rem - b * KTOT;
        int c   = k / 9;
        int rs  = k - c * 9;
        int r   = rs / 3;
        int s   = rs - r * 3;
        patch[(p * NB + b) * KPAD + k] =
            input[((b * CIN + c) << 14) + base_in[p] + r * 128 + s];
    }

    // Work mapping: warp w: ohalf = w&1, batch group = w>>1.
    // lane: o-group = lane&7 (4 channels), batch = (w>>1)*4 + (lane>>3).
    const int lane  = tid & 31;
    const int warp  = tid >> 5;
    const int o4    = (warp & 1) * 32 + (lane & 7) * 4;
    const int b     = (warp >> 1) * 4 + (lane >> 3);

    const float* p0 = patch + b * KPAD;         // pixel 0 stream
    const float* p1 = patch + (NB + b) * KPAD;  // pixel 1 stream

    // f32x2 packed accumulators: a[stream][o-pair]; pair = (o4+0,o4+1)/(o4+2,o4+3)
    unsigned long long a00 = 0ull, a01 = 0ull, a10 = 0ull, a11 = 0ull;

    for (int ch = 0; ch < NCHUNK; ch++) {
        __syncthreads();
        // Stage weight chunk: KC*64 = 9216 floats = 2304 float4, 9 per thread.
        {
            const float4* src = (const float4*)(g_wT + ch * KC * COUT);
            float4*       dst = (float4*)wsh;
#pragma unroll
            for (int i = 0; i < KC * COUT / 4 / THREADS; i++)
                dst[tid + i * THREADS] = src[tid + i * THREADS];
        }
        __syncthreads();

        const int kb = ch * KC;
#pragma unroll 2
        for (int kk = 0; kk < KC; kk += 4) {
            float4 q0 = *(const float4*)(p0 + kb + kk);   // 4 distinct addrs/warp, pad -> 1 wf
            float4 q1 = *(const float4*)(p1 + kb + kk);
            float e0[4] = {q0.x, q0.y, q0.z, q0.w};
            float e1[4] = {q1.x, q1.y, q1.z, q1.w};
#pragma unroll
            for (int j = 0; j < 4; j++) {
                // 8 distinct float4 addrs spanning 128B, replicated x4 -> 1 wf
                ulonglong2 wv = *(const ulonglong2*)(wsh + (kk + j) * COUT + o4);
                unsigned long long d0, d1;
                asm("mov.b64 %0, {%1, %1};" : "=l"(d0) : "f"(e0[j]));
                asm("mov.b64 %0, {%1, %1};" : "=l"(d1) : "f"(e1[j]));
                asm("fma.rn.f32x2 %0, %1, %2, %0;" : "+l"(a00) : "l"(wv.x), "l"(d0));
                asm("fma.rn.f32x2 %0, %1, %2, %0;" : "+l"(a01) : "l"(wv.y), "l"(d0));
                asm("fma.rn.f32x2 %0, %1, %2, %0;" : "+l"(a10) : "l"(wv.x), "l"(d1));
                asm("fma.rn.f32x2 %0, %1, %2, %0;" : "+l"(a11) : "l"(wv.y), "l"(d1));
            }
        }
    }

    // Unpack accumulators.
    float r00x, r00y, r01x, r01y, r10x, r10y, r11x, r11y;
    asm("mov.b64 {%0, %1}, %2;" : "=f"(r00x), "=f"(r00y) : "l"(a00));
    asm("mov.b64 {%0, %1}, %2;" : "=f"(r01x), "=f"(r01y) : "l"(a01));
    asm("mov.b64 {%0, %1}, %2;" : "=f"(r10x), "=f"(r10y) : "l"(a10));
    asm("mov.b64 {%0, %1}, %2;" : "=f"(r11x), "=f"(r11y) : "l"(a11));

    const float4 bb = *(const float4*)(bias + o4);

    if (valid[0]) {
        int px = px0;
        out[(b * COUT + o4 + 0) * NPIX + px] = r00x + bb.x;
        out[(b * COUT + o4 + 1) * NPIX + px] = r00y + bb.y;
        out[(b * COUT + o4 + 2) * NPIX + px] = r01x + bb.z;
        out[(b * COUT + o4 + 3) * NPIX + px] = r01y + bb.w;
    }
    if (valid[1]) {
        int px = px0 + 1;
        out[(b * COUT + o4 + 0) * NPIX + px] = r10x + bb.x;
        out[(b * COUT + o4 + 1) * NPIX + px] = r10y + bb.y;
        out[(b * COUT + o4 + 2) * NPIX + px] = r11x + bb.z;
        out[(b * COUT + o4 + 3) * NPIX + px] = r11y + bb.w;
    }
}

extern "C" void kernel_launch(void* const* d_in, const int* in_sizes, int n_in,
                              void* d_out, int out_size)
{
    const float* input  = (const float*)d_in[0];
    const float* weight = (const float*)d_in[1];
    const float* bias   = (const float*)d_in[2];
    const int*   selh   = (const int*)d_in[3];
    const int*   selw   = (const int*)d_in[4];
    float*       out    = (float*)d_out;

    cudaFuncSetAttribute(sconv_kernel,
                         cudaFuncAttributeMaxDynamicSharedMemorySize, SMEM_BYTES);

    transpose_w_kernel<<<(KTOT * COUT + 255) / 256, 256>>>(weight);
    sconv_kernel<<<(NPIX + 1) / 2, THREADS, SMEM_BYTES>>>(input, bias, selh, selw, out);
}

// round 5
// speedup vs baseline: 3.8817x; 3.8817x over previous
#include <cuda_runtime.h>
#include <cuda_bf16.h>
#include <cstdint>

// SConv2dAvg as GEMM on HMMA (mma.sync bf16, 3-product double-bf16 split).
// D[o,n] = sum_k W[o,k] P[k,n];  n = b*16+px tile of 256; k' = (r*3+s)*64 + c.
// B=16, Cin=64, H=W=128, Cout=64, 3x3, oh=ow=63, stride 2.

#define Y_DIM   63
#define X_TILES 4
#define PX_T    16
#define COUT    64
#define KTOT    576
#define NCH     9
#define THREADS 256
#define STR     72                         // smem row stride in bf16 (144B): conflict-free frags

#define AHI_OFF 0
#define ALO_OFF (64 * STR * 2)             // 9216
#define BHI_OFF (ALO_OFF + 64 * STR * 2)   // 18432
#define BLO_OFF (BHI_OFF + 256 * STR * 2)  // 55296
#define SMEM_TOTAL (BLO_OFF + 256 * STR * 2)  // 92160

// Weight pre-split hi/lo bf16, k-major with k' reorder: [64][576]
__device__ unsigned short g_Ahi[COUT * KTOT];
__device__ unsigned short g_Alo[COUT * KTOT];

__global__ void prep_A_kernel(const float* __restrict__ w) {
    int idx = blockIdx.x * 256 + threadIdx.x;
    if (idx >= COUT * KTOT) return;
    int o  = idx / KTOT;
    int kp = idx - o * KTOT;        // k' = rs*64 + c
    int rs = kp >> 6;
    int c  = kp & 63;
    float v = w[o * KTOT + c * 9 + rs];
    unsigned short hi;
    asm("cvt.rn.bf16.f32 %0, %1;" : "=h"(hi) : "f"(v));
    float rem = v - __uint_as_float(((unsigned)hi) << 16);
    unsigned short lo;
    asm("cvt.rn.bf16.f32 %0, %1;" : "=h"(lo) : "f"(rem));
    g_Ahi[idx] = hi;
    g_Alo[idx] = lo;
}

// pack two f32 -> bf16x2 (x in low half, y in high half)
__device__ __forceinline__ uint32_t pack_bf16x2(float x, float y) {
    uint32_t r;
    asm("cvt.rn.satfinite.bf16x2.f32 %0, %2, %1;" : "=r"(r) : "f"(x), "f"(y));
    return r;
}

#define MMA(acc, a, b)                                                         \
    asm volatile("mma.sync.aligned.m16n8k16.row.col.f32.bf16.bf16.f32 "        \
        "{%0,%1,%2,%3}, {%4,%5,%6,%7}, {%8,%9}, {%0,%1,%2,%3};"                \
        : "+f"((acc)[0]), "+f"((acc)[1]), "+f"((acc)[2]), "+f"((acc)[3])       \
        : "r"((a)[0]), "r"((a)[1]), "r"((a)[2]), "r"((a)[3]),                  \
          "r"((b)[0]), "r"((b)[1]))

__global__ __launch_bounds__(THREADS, 2) void sconv_hmma_kernel(
    const float* __restrict__ input,
    const float* __restrict__ bias,
    const int*   __restrict__ selh,
    const int*   __restrict__ selw,
    float*       __restrict__ out)
{
    extern __shared__ char smem[];

    const int tid  = threadIdx.x;
    const int lane = tid & 31;
    const int w    = tid >> 5;

    const int y   = blockIdx.x / X_TILES;
    const int px0 = (blockIdx.x % X_TILES) * PX_T;

    // ---- gather setup: thread t owns B row n = t  (b = t>>4, pxl = t&15) ----
    const int pxl = tid & 15;
    const int b   = tid >> 4;
    const int pxc = min(px0 + pxl, Y_DIM - 1);
    const int sh  = selh[y * Y_DIM + pxc];
    const int sw  = selw[y * Y_DIM + pxc];
    const float* pbase = input + (b << 20) + (2 * y + sh) * 128 + 2 * pxc + sw;

    float acc[4][4][4];
#pragma unroll
    for (int i = 0; i < 4; i++)
#pragma unroll
        for (int j = 0; j < 4; j++)
#pragma unroll
            for (int q = 0; q < 4; q++) acc[i][j][q] = 0.f;

    const int fq = lane & 3;        // k-pair selector within frags
    const int fr = lane >> 2;       // row selector within frags

    for (int ch = 0; ch < NCH; ch++) {
        __syncthreads();

        // stage A chunk hi/lo: 64 rows x 64 bf16 -> smem stride 72
#pragma unroll
        for (int i = 0; i < 4; i++) {
            int e = tid + i * THREADS;          // 0..1023 over 2 buffers
            int buf = e >> 9;                   // 0: hi, 1: lo
            int e2  = e & 511;
            int m   = e2 >> 3;
            int q   = e2 & 7;
            const char* src = (const char*)(buf ? g_Alo : g_Ahi) + m * (KTOT * 2) + ch * 128 + q * 16;
            *(uint4*)(smem + (buf ? ALO_OFF : AHI_OFF) + m * (STR * 2) + q * 16) =
                *(const uint4*)src;
        }

        // gather this thread's 64 c-values of plane (r,s), split hi/lo, store rows
        const float* p = pbase + (ch / 3) * 128 + (ch % 3);
#pragma unroll
        for (int cb = 0; cb < 8; cb++) {
            float v[8];
#pragma unroll
            for (int j = 0; j < 8; j++)
                v[j] = __ldg(p + ((cb * 8 + j) << 14));
            uint32_t hp[4], lp[4];
#pragma unroll
            for (int q = 0; q < 4; q++) {
                float a0 = v[2 * q], a1 = v[2 * q + 1];
                hp[q] = pack_bf16x2(a0, a1);
                float r0 = a0 - __uint_as_float(hp[q] << 16);
                float r1 = a1 - __uint_as_float(hp[q] & 0xFFFF0000u);
                lp[q] = pack_bf16x2(r0, r1);
            }
            *(uint4*)(smem + BHI_OFF + tid * (STR * 2) + cb * 16) = make_uint4(hp[0], hp[1], hp[2], hp[3]);
            *(uint4*)(smem + BLO_OFF + tid * (STR * 2) + cb * 16) = make_uint4(lp[0], lp[1], lp[2], lp[3]);
        }
        __syncthreads();

        // ---- compute: 4 k16 steps over this 64-k chunk ----
#pragma unroll
        for (int kq = 0; kq < 4; kq++) {
            const int koff = (kq * 16 + 2 * fq) * 2;   // byte offset of k within row

            uint32_t bh[4][2], bl[4][2];
#pragma unroll
            for (int nf = 0; nf < 4; nf++) {
                int nrow = w * 32 + nf * 8 + fr;
                const char* ph = smem + BHI_OFF + nrow * (STR * 2) + koff;
                const char* pl = smem + BLO_OFF + nrow * (STR * 2) + koff;
                bh[nf][0] = *(const uint32_t*)ph;
                bh[nf][1] = *(const uint32_t*)(ph + 16);
                bl[nf][0] = *(const uint32_t*)pl;
                bl[nf][1] = *(const uint32_t*)(pl + 16);
            }

#pragma unroll
            for (int mf = 0; mf < 4; mf++) {
                int mrow = mf * 16 + fr;
                const char* ph = smem + AHI_OFF + mrow * (STR * 2) + koff;
                const char* pl = smem + ALO_OFF + mrow * (STR * 2) + koff;
                uint32_t ah[4], al[4];
                ah[0] = *(const uint32_t*)ph;
                ah[1] = *(const uint32_t*)(ph + 8 * (STR * 2));
                ah[2] = *(const uint32_t*)(ph + 16);
                ah[3] = *(const uint32_t*)(ph + 8 * (STR * 2) + 16);
                al[0] = *(const uint32_t*)pl;
                al[1] = *(const uint32_t*)(pl + 8 * (STR * 2));
                al[2] = *(const uint32_t*)(pl + 16);
                al[3] = *(const uint32_t*)(pl + 8 * (STR * 2) + 16);
#pragma unroll
                for (int nf = 0; nf < 4; nf++) {
                    MMA(acc[mf][nf], ah, bh[nf]);
                    MMA(acc[mf][nf], ah, bl[nf]);
                    MMA(acc[mf][nf], al, bh[nf]);
                }
            }
        }
    }

    // ---- epilogue: scalar stores (out rows have odd stride 3969 -> no 8B alignment).
    // n = w*32 + nf*8 + 2*fq (+1); o = mf*16 + fr (+8)
    const int npx  = min(PX_T, Y_DIM - px0);   // valid pxl in [0, npx)
    const int ybase = y * Y_DIM + px0;

#pragma unroll
    for (int mf = 0; mf < 4; mf++) {
        const int o = mf * 16 + fr;
        const float bo0 = __ldg(bias + o);
        const float bo8 = __ldg(bias + o + 8);
#pragma unroll
        for (int nf = 0; nf < 4; nf++) {
            int n    = w * 32 + nf * 8 + 2 * fq;
            int bcol = n >> 4;
            int pp   = n & 15;
            long base0 = ((long)(bcol * COUT + o)) * (Y_DIM * Y_DIM) + ybase + pp;
            long base8 = base0 + 8L * (Y_DIM * Y_DIM);
            if (pp < npx) {
                out[base0] = acc[mf][nf][0] + bo0;
                out[base8] = acc[mf][nf][2] + bo8;
            }
            if (pp + 1 < npx) {
                out[base0 + 1] = acc[mf][nf][1] + bo0;
                out[base8 + 1] = acc[mf][nf][3] + bo8;
            }
        }
    }
}

extern "C" void kernel_launch(void* const* d_in, const int* in_sizes, int n_in,
                              void* d_out, int out_size)
{
    const float* input  = (const float*)d_in[0];
    const float* weight = (const float*)d_in[1];
    const float* bias   = (const float*)d_in[2];
    const int*   selh   = (const int*)d_in[3];
    const int*   selw   = (const int*)d_in[4];
    float*       out    = (float*)d_out;

    cudaFuncSetAttribute(sconv_hmma_kernel,
                         cudaFuncAttributeMaxDynamicSharedMemorySize, SMEM_TOTAL);

    prep_A_kernel<<<(COUT * KTOT + 255) / 256, 256>>>(weight);
    sconv_hmma_kernel<<<Y_DIM * X_TILES, THREADS, SMEM_TOTAL>>>(input, bias, selh, selw, out);
}